// round 2
// baseline (speedup 1.0000x reference)
#include <cuda_runtime.h>
#include <cstdint>

// Inverse index table: inv[f] = k such that idx[k] == f, else -1.
#define INV_CAP 8192
__device__ int g_inv[INV_CAP];

__global__ void init_inv_kernel(int F) {
    int i = blockIdx.x * blockDim.x + threadIdx.x;
    if (i < F) g_inv[i] = -1;
}

__global__ void fill_inv_kernel(const int* __restrict__ idx, int K) {
    int k = blockIdx.x * blockDim.x + threadIdx.x;
    if (k < K) {
        int f = idx[k];
        if (f >= 0 && f < INV_CAP) g_inv[f] = k;
    }
}

// One block (F threads) per row of [rows, F]. Thread f handles element f.
// comp = (sum over gathered channels of dropped x) / K, added to all gathered
// channels (dropped ones become exactly comp); non-gathered pass through.
__global__ __launch_bounds__(256) void dropout_partial_kernel(
    const float* __restrict__ X,
    const int* __restrict__ mask,   // [rows, K] int32, nonzero = dropped
    float* __restrict__ out,
    int K, int F, float inv_K)
{
    __shared__ float warp_sums[8];
    __shared__ float s_comp;

    const int row = blockIdx.x;
    const int f   = threadIdx.x;
    const size_t base = (size_t)row * (size_t)F;

    float x = X[base + f];

    int k = g_inv[f];
    int m = 0;
    if (k >= 0) m = mask[(size_t)row * (size_t)K + (size_t)k];

    // dropped mass contribution
    float d = (k >= 0 && m != 0) ? x : 0.0f;

    // warp reduce
    #pragma unroll
    for (int off = 16; off > 0; off >>= 1)
        d += __shfl_xor_sync(0xFFFFFFFFu, d, off);

    const int lane = threadIdx.x & 31;
    const int wid  = threadIdx.x >> 5;
    if (lane == 0) warp_sums[wid] = d;
    __syncthreads();

    if (wid == 0) {
        int nwarps = (blockDim.x + 31) >> 5;
        float s = (lane < nwarps) ? warp_sums[lane] : 0.0f;
        #pragma unroll
        for (int off = 4; off > 0; off >>= 1)
            s += __shfl_xor_sync(0xFFFFFFFFu, s, off);
        if (lane == 0) s_comp = s * inv_K;
    }
    __syncthreads();

    float comp = s_comp;

    float o;
    if (k >= 0) {
        o = (m != 0 ? 0.0f : x) + comp;
    } else {
        o = x;
    }
    out[base + f] = o;
}

extern "C" void kernel_launch(void* const* d_in, const int* in_sizes, int n_in,
                              void* d_out, int out_size)
{
    const float* X    = (const float*)d_in[0];
    const int*   idx  = (const int*)d_in[1];
    const int*   mask = (const int*)d_in[2];
    float*       out  = (float*)d_out;

    const int  K    = in_sizes[1];                     // 128
    const long rows = (long)in_sizes[2] / K;           // B*C*T = 262144
    const int  F    = (int)((long)in_sizes[0] / rows); // 256

    init_inv_kernel<<<(F + 255) / 256, 256>>>(F);
    fill_inv_kernel<<<(K + 255) / 256, 256>>>(idx, K);

    dropout_partial_kernel<<<(unsigned)rows, F>>>(X, mask, out, K, F, 1.0f / (float)K);
}

// round 3
// speedup vs baseline: 2.6039x; 2.6039x over previous
#include <cuda_runtime.h>
#include <cstdint>

// Inverse index table: inv[f] = k such that idx[k] == f, else -1.
#define INV_CAP 8192
__device__ int g_inv[INV_CAP];

__global__ void init_inv_kernel(int F) {
    int i = blockIdx.x * blockDim.x + threadIdx.x;
    if (i < F) g_inv[i] = -1;
}

__global__ void fill_inv_kernel(const int* __restrict__ idx, int K) {
    int k = blockIdx.x * blockDim.x + threadIdx.x;
    if (k < K) {
        int f = idx[k];
        if (f >= 0 && f < INV_CAP) g_inv[f] = k;
    }
}

// ---------------------------------------------------------------------------
// Fast path: F == 256, K == 128. One warp per row, float4/int4 vectorized,
// warp-shuffle reduction, no block barriers in the hot loop.
// ---------------------------------------------------------------------------
__global__ __launch_bounds__(256) void dropout_fast_kernel(
    const float4* __restrict__ X4,   // rows * 64 float4
    const int4*  __restrict__ M4,    // rows * 32 int4
    float4*      __restrict__ O4,
    long rows, float inv_K)
{
    __shared__ int s_inv[256];
    __shared__ int s_mask[8][128];

    const int tid = threadIdx.x;
    s_inv[tid] = g_inv[tid];
    __syncthreads();

    const int warp = tid >> 5;
    const int lane = tid & 31;
    const long row = (long)blockIdx.x * 8 + warp;
    if (row >= rows) return;

    const long xbase = row * 64;   // 256 floats = 64 float4
    const long mbase = row * 32;   // 128 ints  = 32 int4

    // Front-batched wide loads: high MLP.
    float4 a  = X4[xbase + lane];
    float4 b  = X4[xbase + 32 + lane];
    int4   mv = M4[mbase + lane];

    *reinterpret_cast<int4*>(&s_mask[warp][lane * 4]) = mv;
    __syncwarp();

    const int fa = lane * 4;        // channels of a
    const int fb = 128 + lane * 4;  // channels of b

    float xa[4] = {a.x, a.y, a.z, a.w};
    float xb[4] = {b.x, b.y, b.z, b.w};
    int ka[4], kb[4], ma[4], mb[4];

    float d = 0.0f;
    #pragma unroll
    for (int j = 0; j < 4; j++) {
        ka[j] = s_inv[fa + j];
        kb[j] = s_inv[fb + j];
        ma[j] = (ka[j] >= 0) ? s_mask[warp][ka[j]] : 0;
        mb[j] = (kb[j] >= 0) ? s_mask[warp][kb[j]] : 0;
        if (ma[j]) d += xa[j];
        if (mb[j]) d += xb[j];
    }

    #pragma unroll
    for (int off = 16; off > 0; off >>= 1)
        d += __shfl_xor_sync(0xFFFFFFFFu, d, off);
    const float comp = d * inv_K;

    float oa[4], ob[4];
    #pragma unroll
    for (int j = 0; j < 4; j++) {
        oa[j] = (ka[j] >= 0) ? ((ma[j] ? 0.0f : xa[j]) + comp) : xa[j];
        ob[j] = (kb[j] >= 0) ? ((mb[j] ? 0.0f : xb[j]) + comp) : xb[j];
    }

    O4[xbase + lane]      = make_float4(oa[0], oa[1], oa[2], oa[3]);
    O4[xbase + 32 + lane] = make_float4(ob[0], ob[1], ob[2], ob[3]);
}

// ---------------------------------------------------------------------------
// Generic fallback (known-correct from R2): one block per row.
// ---------------------------------------------------------------------------
__global__ __launch_bounds__(1024) void dropout_generic_kernel(
    const float* __restrict__ X,
    const int* __restrict__ mask,
    float* __restrict__ out,
    int K, int F, float inv_K)
{
    __shared__ float warp_sums[32];
    __shared__ float s_comp;

    const int row = blockIdx.x;
    const int f   = threadIdx.x;
    const size_t base = (size_t)row * (size_t)F;

    float x = 0.0f;
    int k = -1, m = 0;
    if (f < F) {
        x = X[base + f];
        k = g_inv[f];
        if (k >= 0) m = mask[(size_t)row * (size_t)K + (size_t)k];
    }

    float d = (k >= 0 && m != 0) ? x : 0.0f;
    #pragma unroll
    for (int off = 16; off > 0; off >>= 1)
        d += __shfl_xor_sync(0xFFFFFFFFu, d, off);

    const int lane = threadIdx.x & 31;
    const int wid  = threadIdx.x >> 5;
    if (lane == 0) warp_sums[wid] = d;
    __syncthreads();

    if (wid == 0) {
        int nwarps = (blockDim.x + 31) >> 5;
        float s = (lane < nwarps) ? warp_sums[lane] : 0.0f;
        #pragma unroll
        for (int off = 16; off > 0; off >>= 1)
            s += __shfl_xor_sync(0xFFFFFFFFu, s, off);
        if (lane == 0) s_comp = s * inv_K;
    }
    __syncthreads();

    if (f < F) {
        float comp = s_comp;
        out[base + f] = (k >= 0) ? ((m != 0 ? 0.0f : x) + comp) : x;
    }
}

extern "C" void kernel_launch(void* const* d_in, const int* in_sizes, int n_in,
                              void* d_out, int out_size)
{
    const float* X    = (const float*)d_in[0];
    const int*   idx  = (const int*)d_in[1];
    const int*   mask = (const int*)d_in[2];
    float*       out  = (float*)d_out;

    const int  K    = in_sizes[1];                     // 128
    const long rows = (long)in_sizes[2] / K;           // B*C*T = 262144
    const int  F    = (int)((long)in_sizes[0] / rows); // 256

    init_inv_kernel<<<(F + 255) / 256, 256>>>(F);
    fill_inv_kernel<<<(K + 255) / 256, 256>>>(idx, K);

    if (F == 256 && K == 128) {
        const unsigned nblocks = (unsigned)((rows + 7) / 8);
        dropout_fast_kernel<<<nblocks, 256>>>(
            (const float4*)X, (const int4*)mask, (float4*)out, rows, 1.0f / (float)K);
    } else {
        int threads = ((F + 31) / 32) * 32;
        if (threads > 1024) threads = 1024;  // (F>1024 unsupported; shapes here are fixed)
        dropout_generic_kernel<<<(unsigned)rows, threads>>>(X, mask, out, K, F, 1.0f / (float)K);
    }
}

// round 4
// speedup vs baseline: 2.7118x; 1.0415x over previous
#include <cuda_runtime.h>
#include <cstdint>

// ---------------------------------------------------------------------------
// Generic-path inverse table (only used by the fallback kernel).
// ---------------------------------------------------------------------------
#define INV_CAP 8192
__device__ int g_inv[INV_CAP];

__global__ void build_inv_kernel(const int* __restrict__ idx, int K, int F) {
    int i = blockIdx.x * blockDim.x + threadIdx.x;
    if (i < F) g_inv[i] = -1;
    __syncthreads();
    if (i < K) {
        int f = idx[i];
        if (f >= 0 && f < INV_CAP) g_inv[f] = i;
    }
}

// ---------------------------------------------------------------------------
// Fast path: F == 256, K <= 256. One warp per row, float4/int4 vectorized,
// inverse table built per-block in smem (no prologue kernels), loads
// front-batched ahead of the barriers to hide DRAM latency.
// ---------------------------------------------------------------------------
__global__ __launch_bounds__(256) void dropout_fast_kernel(
    const float4* __restrict__ X4,   // rows * 64 float4
    const int4*  __restrict__ M4,    // rows * K/4 int4
    const int*   __restrict__ idx,   // [K]
    float4*      __restrict__ O4,
    long rows, int K, float inv_K)
{
    __shared__ int s_inv[256];
    __shared__ int s_mask[8][128];

    const int tid  = threadIdx.x;
    const int warp = tid >> 5;
    const int lane = tid & 31;
    const long row = (long)blockIdx.x * 8 + warp;
    const bool valid = row < rows;

    const long xbase = valid ? row * 64 : 0;          // 256 floats = 64 float4
    const long mbase = valid ? row * (K >> 2) : 0;    // K ints = K/4 int4

    // Front-batched wide loads (high MLP; latency overlaps the smem setup).
    const float4 a  = __ldcs(&X4[xbase + lane]);
    const float4 b  = __ldcs(&X4[xbase + 32 + lane]);
    const int4   mv = __ldcs(&M4[mbase + lane]);
    const int idx_f = (tid < K) ? idx[tid] : -1;

    // Build inverse table in smem.
    s_inv[tid] = -1;
    __syncthreads();
    if (idx_f >= 0 && idx_f < 256) s_inv[idx_f] = tid;
    *reinterpret_cast<int4*>(&s_mask[warp][lane * 4]) = mv;
    __syncthreads();

    const int fa = lane * 4;        // channels of a
    const int fb = 128 + lane * 4;  // channels of b

    float xa[4] = {a.x, a.y, a.z, a.w};
    float xb[4] = {b.x, b.y, b.z, b.w};
    int ka[4], kb[4], ma[4], mb[4];

    float d = 0.0f;
    #pragma unroll
    for (int j = 0; j < 4; j++) {
        ka[j] = s_inv[fa + j];
        kb[j] = s_inv[fb + j];
        ma[j] = (ka[j] >= 0) ? s_mask[warp][ka[j]] : 0;
        mb[j] = (kb[j] >= 0) ? s_mask[warp][kb[j]] : 0;
        if (ma[j]) d += xa[j];
        if (mb[j]) d += xb[j];
    }

    #pragma unroll
    for (int off = 16; off > 0; off >>= 1)
        d += __shfl_xor_sync(0xFFFFFFFFu, d, off);
    const float comp = d * inv_K;

    float oa[4], ob[4];
    #pragma unroll
    for (int j = 0; j < 4; j++) {
        oa[j] = (ka[j] >= 0) ? ((ma[j] ? 0.0f : xa[j]) + comp) : xa[j];
        ob[j] = (kb[j] >= 0) ? ((mb[j] ? 0.0f : xb[j]) + comp) : xb[j];
    }

    if (valid) {
        __stcs(&O4[xbase + lane],      make_float4(oa[0], oa[1], oa[2], oa[3]));
        __stcs(&O4[xbase + 32 + lane], make_float4(ob[0], ob[1], ob[2], ob[3]));
    }
}

// ---------------------------------------------------------------------------
// Generic fallback: one block per row (uses g_inv built by prologue).
// ---------------------------------------------------------------------------
__global__ __launch_bounds__(1024) void dropout_generic_kernel(
    const float* __restrict__ X,
    const int* __restrict__ mask,
    float* __restrict__ out,
    int K, int F, float inv_K)
{
    __shared__ float warp_sums[32];
    __shared__ float s_comp;

    const int row = blockIdx.x;
    const int f   = threadIdx.x;
    const size_t base = (size_t)row * (size_t)F;

    float x = 0.0f;
    int k = -1, m = 0;
    if (f < F) {
        x = X[base + f];
        k = g_inv[f];
        if (k >= 0) m = mask[(size_t)row * (size_t)K + (size_t)k];
    }

    float d = (k >= 0 && m != 0) ? x : 0.0f;
    #pragma unroll
    for (int off = 16; off > 0; off >>= 1)
        d += __shfl_xor_sync(0xFFFFFFFFu, d, off);

    const int lane = threadIdx.x & 31;
    const int wid  = threadIdx.x >> 5;
    if (lane == 0) warp_sums[wid] = d;
    __syncthreads();

    if (wid == 0) {
        int nwarps = (blockDim.x + 31) >> 5;
        float s = (lane < nwarps) ? warp_sums[lane] : 0.0f;
        #pragma unroll
        for (int off = 16; off > 0; off >>= 1)
            s += __shfl_xor_sync(0xFFFFFFFFu, s, off);
        if (lane == 0) s_comp = s * inv_K;
    }
    __syncthreads();

    if (f < F) {
        float comp = s_comp;
        out[base + f] = (k >= 0) ? ((m != 0 ? 0.0f : x) + comp) : x;
    }
}

extern "C" void kernel_launch(void* const* d_in, const int* in_sizes, int n_in,
                              void* d_out, int out_size)
{
    const float* X    = (const float*)d_in[0];
    const int*   idx  = (const int*)d_in[1];
    const int*   mask = (const int*)d_in[2];
    float*       out  = (float*)d_out;

    const int  K    = in_sizes[1];                     // 128
    const long rows = (long)in_sizes[2] / K;           // B*C*T = 262144
    const int  F    = (int)((long)in_sizes[0] / rows); // 256

    if (F == 256 && K <= 256 && (K & 3) == 0) {
        const unsigned nblocks = (unsigned)((rows + 7) / 8);
        dropout_fast_kernel<<<nblocks, 256>>>(
            (const float4*)X, (const int4*)mask, idx, (float4*)out,
            rows, K, 1.0f / (float)K);
    } else {
        int fthreads = F > 256 ? ((F + 255) / 256) * 256 : 256;
        if (fthreads > 1024) fthreads = 1024;
        build_inv_kernel<<<(F > K ? (F + 255) / 256 : (K + 255) / 256), 256>>>(idx, K, F);
        int threads = ((F + 31) / 32) * 32;
        if (threads > 1024) threads = 1024;
        dropout_generic_kernel<<<(unsigned)rows, threads>>>(X, mask, out, K, F, 1.0f / (float)K);
    }
}